// round 10
// baseline (speedup 1.0000x reference)
#include <cuda_runtime.h>
#include <cuda_fp16.h>

#define NM 12000
#define ND 10000
#define DIM 64
#define FEAT 512
#define EMAX 1000000
#define EPAD 1100000
#define LAYERS 3

#define PROJ_TILE 64
#define GRID_PROJ_M ((NM + PROJ_TILE - 1) / PROJ_TILE)   // 188
#define GRID_PROJ_D ((ND + PROJ_TILE - 1) / PROJ_TILE)   // 157
#define GRID_PB (GRID_PROJ_M + GRID_PROJ_D)              // 345
#define NCOUNT 512            // histogram blocks fused into proj launch

// ---------------- device scratch ----------------
__device__ float   g_memb[NM * DIM];
__device__ float   g_demb[ND * DIM];
__device__ __half2 g_membh[NM * DIM / 2];   // half mirror of embeddings
__device__ __half2 g_dembh[ND * DIM / 2];
__device__ __half2 g_pmh[NM * DIM / 2];     // half MLP partials (+b1 on m side)
__device__ __half2 g_pdh[ND * DIM / 2];
__device__ float   g_rs_m[NM];
__device__ float   g_rs_d[ND];
__device__ int     g_off_m[NM];         // 8-aligned row starts
__device__ int     g_off_d[ND];
__device__ int     g_cur_m[NM];         // counts -> cursors -> row ends
__device__ int     g_cur_d[ND];
__device__ int     g_col_m[EPAD];
__device__ float   g_val_m[EPAD];
__device__ int     g_col_d[EPAD];
__device__ float   g_val_d[EPAD];

__device__ __forceinline__ float tanh_fast(float x) {
    float xc = fminf(fmaxf(x, -12.f), 12.f);
    float e2 = __expf(2.f * xc);
    return __fdividef(e2 - 1.f, e2 + 1.f);
}
__device__ __forceinline__ float tanh_approx(float x) {
    float y;
    asm("tanh.approx.f32 %0, %1;" : "=f"(y) : "f"(x));
    return y;
}
__device__ __forceinline__ unsigned cvt_tf32(float f) {
    unsigned u;
    asm("cvt.rna.tf32.f32 %0, %1;" : "=r"(u) : "f"(f));
    return u;
}
__device__ __forceinline__ void mma_tf32(float* c, const unsigned* a, const unsigned* b) {
    asm("mma.sync.aligned.m16n8k8.row.col.f32.tf32.tf32.f32 "
        "{%0,%1,%2,%3}, {%4,%5,%6,%7}, {%8,%9}, {%0,%1,%2,%3};"
        : "+f"(c[0]), "+f"(c[1]), "+f"(c[2]), "+f"(c[3])
        : "r"(a[0]), "r"(a[1]), "r"(a[2]), "r"(a[3]), "r"(b[0]), "r"(b[1]));
}

// ---------------- init ----------------
__global__ void zero_kernel() {
    int i = blockIdx.x * blockDim.x + threadIdx.x;
    if (i < NM) g_cur_m[i] = 0;
    if (i < ND) g_cur_d[i] = 0;
}

// ---------------- split-tf32 MMA projection (m+d) + fused histogram -------
// 3-MMA error compensation: acc = ah*bh + ah*bl + al*bh  (~fp32 accuracy)
// blocks [0, GRID_PB): GEMM tiles 64x64; blocks [GRID_PB, +NCOUNT): histogram
__global__ __launch_bounds__(128) void proj_mma_kernel(const float* __restrict__ Am,
                                                       const float* __restrict__ Ad,
                                                       const float* __restrict__ Wm,
                                                       const float* __restrict__ Wd,
                                                       const int* __restrict__ mi,
                                                       const int* __restrict__ di,
                                                       int E) {
    int bid = blockIdx.x;
    int tid = threadIdx.x;

    if (bid >= GRID_PB) {
        int b = bid - GRID_PB;
        for (int e = b * 128 + tid; e < E; e += NCOUNT * 128) {
            atomicAdd(&g_cur_m[mi[e]], 1);
            atomicAdd(&g_cur_d[di[e]], 1);
        }
        return;
    }

    int which = (bid >= GRID_PROJ_M) ? 1 : 0;
    int blk = which ? (bid - GRID_PROJ_M) : bid;
    const float* A = which ? Ad : Am;
    const float* W = which ? Wd : Wm;
    float* C = which ? g_demb : g_memb;
    __half2* Ch = which ? g_dembh : g_membh;
    int Mrows = which ? ND : NM;
    int row0 = blk * PROJ_TILE;

    __shared__ unsigned As[2][64 * 36];   // [hi/lo], stride 36 conflict-free
    __shared__ unsigned Ws[2][64 * 36];

    int lane = tid & 31;
    int warp = tid >> 5;
    int w0 = warp >> 1;      // row half (0/1)
    int w1 = warp & 1;       // col half (0/1)
    int g = lane >> 2, t = lane & 3;

    float acc[2][4][4];
#pragma unroll
    for (int i = 0; i < 2; i++)
#pragma unroll
        for (int j = 0; j < 4; j++)
#pragma unroll
            for (int k = 0; k < 4; k++) acc[i][j][k] = 0.f;

    for (int kc = 0; kc < FEAT; kc += 32) {
        // A tile 64x32 split hi/lo
#pragma unroll
        for (int p = 0; p < 4; p++) {
            int idx = p * 128 + tid;       // 0..511 float4 slots
            int r = idx >> 3, kq = idx & 7;
            int grow = row0 + r;
            float4 v = make_float4(0.f, 0.f, 0.f, 0.f);
            if (grow < Mrows)
                v = *(const float4*)(A + (size_t)grow * FEAT + kc + kq * 4);
            unsigned h0 = cvt_tf32(v.x), h1 = cvt_tf32(v.y);
            unsigned h2 = cvt_tf32(v.z), h3 = cvt_tf32(v.w);
            unsigned* dh = &As[0][r * 36 + kq * 4];
            dh[0] = h0; dh[1] = h1; dh[2] = h2; dh[3] = h3;
            unsigned* dl = &As[1][r * 36 + kq * 4];
            dl[0] = cvt_tf32(v.x - __uint_as_float(h0));
            dl[1] = cvt_tf32(v.y - __uint_as_float(h1));
            dl[2] = cvt_tf32(v.z - __uint_as_float(h2));
            dl[3] = cvt_tf32(v.w - __uint_as_float(h3));
        }
        // W tile 64x32 split hi/lo
#pragma unroll
        for (int p = 0; p < 4; p++) {
            int idx = p * 128 + tid;
            int c = idx >> 3, kq = idx & 7;
            float4 v = *(const float4*)(W + (size_t)c * FEAT + kc + kq * 4);
            unsigned h0 = cvt_tf32(v.x), h1 = cvt_tf32(v.y);
            unsigned h2 = cvt_tf32(v.z), h3 = cvt_tf32(v.w);
            unsigned* dh = &Ws[0][c * 36 + kq * 4];
            dh[0] = h0; dh[1] = h1; dh[2] = h2; dh[3] = h3;
            unsigned* dl = &Ws[1][c * 36 + kq * 4];
            dl[0] = cvt_tf32(v.x - __uint_as_float(h0));
            dl[1] = cvt_tf32(v.y - __uint_as_float(h1));
            dl[2] = cvt_tf32(v.z - __uint_as_float(h2));
            dl[3] = cvt_tf32(v.w - __uint_as_float(h3));
        }
        __syncthreads();
#pragma unroll
        for (int kk = 0; kk < 32; kk += 8) {
            unsigned a[2][2][4], b[2][4][2];   // [hi/lo][m2 or ni][frag]
#pragma unroll
            for (int s = 0; s < 2; s++) {
#pragma unroll
                for (int m2 = 0; m2 < 2; m2++) {
                    int r = w0 * 32 + m2 * 16;
                    a[s][m2][0] = As[s][(r + g) * 36 + kk + t];
                    a[s][m2][1] = As[s][(r + g + 8) * 36 + kk + t];
                    a[s][m2][2] = As[s][(r + g) * 36 + kk + t + 4];
                    a[s][m2][3] = As[s][(r + g + 8) * 36 + kk + t + 4];
                }
#pragma unroll
                for (int ni = 0; ni < 4; ni++) {
                    int c = w1 * 32 + ni * 8;
                    b[s][ni][0] = Ws[s][(c + g) * 36 + kk + t];
                    b[s][ni][1] = Ws[s][(c + g) * 36 + kk + t + 4];
                }
            }
#pragma unroll
            for (int m2 = 0; m2 < 2; m2++)
#pragma unroll
                for (int ni = 0; ni < 4; ni++) {
                    mma_tf32(acc[m2][ni], a[0][m2], b[1][ni]);  // hi*lo
                    mma_tf32(acc[m2][ni], a[1][m2], b[0][ni]);  // lo*hi
                    mma_tf32(acc[m2][ni], a[0][m2], b[0][ni]);  // hi*hi
                }
        }
        __syncthreads();
    }

    // epilogue: fp32 emb + half mirror
#pragma unroll
    for (int m2 = 0; m2 < 2; m2++) {
#pragma unroll
        for (int rr = 0; rr < 2; rr++) {
            int grow = row0 + w0 * 32 + m2 * 16 + g + rr * 8;
            if (grow < Mrows) {
#pragma unroll
                for (int ni = 0; ni < 4; ni++) {
                    float c0 = acc[m2][ni][rr * 2 + 0];
                    float c1 = acc[m2][ni][rr * 2 + 1];
                    int col = w1 * 32 + ni * 8 + 2 * t;
                    *(float2*)(C + (size_t)grow * DIM + col) = make_float2(c0, c1);
                    Ch[(size_t)grow * 32 + (col >> 1)] =
                        __float22half2_rn(make_float2(c0, c1));
                }
            }
        }
    }
}

// ---------------- exclusive scan with 8-alignment padding -----------------
__global__ void scan_kernel() {
    int which = blockIdx.x;
    int n = which ? ND : NM;
    int* cnt = which ? g_cur_d : g_cur_m;
    int* off = which ? g_off_d : g_off_m;
    __shared__ int part[1024];
    int t = threadIdx.x;
    int nth = n >> 4;
    int base = t << 4;

    int4 c[4];
    int s = 0;
    if (t < nth) {
#pragma unroll
        for (int q = 0; q < 4; q++)
            c[q] = *(const int4*)(cnt + base + q * 4);
        const int* cp = (const int*)c;
#pragma unroll
        for (int q = 0; q < 16; q++) s += (cp[q] + 7) & ~7;
    }
    part[t] = s;
    __syncthreads();
    for (int dd = 1; dd < 1024; dd <<= 1) {
        int v = (t >= dd) ? part[t - dd] : 0;
        __syncthreads();
        part[t] += v;
        __syncthreads();
    }
    if (t < nth) {
        int run = (t == 0) ? 0 : part[t - 1];
        const int* cp = (const int*)c;
        int o[16];
#pragma unroll
        for (int q = 0; q < 16; q++) { o[q] = run; run += (cp[q] + 7) & ~7; }
#pragma unroll
        for (int q = 0; q < 4; q++) {
            *(int4*)(off + base + q * 4) = ((const int4*)o)[q];
            *(int4*)(cnt + base + q * 4) = ((const int4*)o)[q];
        }
    }
}

// ---------------- per-node MLP partials -> half2 (m and d merged) ---------
__global__ __launch_bounds__(256) void pre_mlp_both_kernel(const float* __restrict__ W1,
                                                           const float* __restrict__ b1) {
    int which = (blockIdx.x >= GRID_PROJ_M) ? 1 : 0;
    int blk = which ? (blockIdx.x - GRID_PROJ_M) : blockIdx.x;
    const float* X = which ? g_demb : g_memb;
    __half2* P = which ? g_pdh : g_pmh;
    int Mrows = which ? ND : NM;
    int koff = which ? 64 : 0;

    __shared__ float As[PROJ_TILE * 33];
    __shared__ float WsT[32 * 64];
    int tid = threadIdx.x;
    int tx = tid & 15, ty = tid >> 4;
    int row0 = blk * PROJ_TILE;

    float acc[4][4];
#pragma unroll
    for (int i = 0; i < 4; i++)
#pragma unroll
        for (int j = 0; j < 4; j++) acc[i][j] = 0.f;

    for (int kc = 0; kc < DIM; kc += 32) {
#pragma unroll
        for (int p = 0; p < 2; p++) {
            int idx = p * 256 + tid;
            int r = idx >> 3;
            int kq = idx & 7;
            int grow = row0 + r;
            float4 v = make_float4(0.f, 0.f, 0.f, 0.f);
            if (grow < Mrows)
                v = *(const float4*)(X + (size_t)grow * DIM + kc + kq * 4);
            float* dst = &As[r * 33 + kq * 4];
            dst[0] = fmaxf(v.x, 0.f); dst[1] = fmaxf(v.y, 0.f);
            dst[2] = fmaxf(v.z, 0.f); dst[3] = fmaxf(v.w, 0.f);
        }
#pragma unroll
        for (int p = 0; p < 2; p++) {
            int idx = p * 256 + tid;
            int c = idx >> 3;
            int kq = idx & 7;
            float4 v = *(const float4*)(W1 + (size_t)c * 128 + koff + kc + kq * 4);
            WsT[(kq * 4 + 0) * 64 + c] = v.x;
            WsT[(kq * 4 + 1) * 64 + c] = v.y;
            WsT[(kq * 4 + 2) * 64 + c] = v.z;
            WsT[(kq * 4 + 3) * 64 + c] = v.w;
        }
        __syncthreads();
#pragma unroll 8
        for (int k = 0; k < 32; k++) {
            float4 w = *(const float4*)&WsT[k * 64 + tx * 4];
#pragma unroll
            for (int i = 0; i < 4; i++) {
                float a = As[(ty * 4 + i) * 33 + k];
                acc[i][0] += a * w.x; acc[i][1] += a * w.y;
                acc[i][2] += a * w.z; acc[i][3] += a * w.w;
            }
        }
        __syncthreads();
    }
#pragma unroll
    for (int i = 0; i < 4; i++) {
        int grow = row0 + ty * 4 + i;
        if (grow < Mrows) {
            float4 v = make_float4(acc[i][0], acc[i][1], acc[i][2], acc[i][3]);
            if (!which) {   // fold bias into m-side partial
                float4 bb = *(const float4*)(b1 + tx * 4);
                v.x += bb.x; v.y += bb.y; v.z += bb.z; v.w += bb.w;
            }
            P[(size_t)grow * 32 + tx * 2 + 0] = __float22half2_rn(make_float2(v.x, v.y));
            P[(size_t)grow * 32 + tx * 2 + 1] = __float22half2_rn(make_float2(v.z, v.w));
        }
    }
}

// ---------------- per-edge: gather half partials, tanh, dot, exp, scatter --
__global__ __launch_bounds__(256) void edge_csr_kernel(const float* __restrict__ W2,
                                                       const int* __restrict__ mi,
                                                       const int* __restrict__ di,
                                                       int E) {
    __shared__ float sW2[64];
    int tid = threadIdx.x;
    if (tid < 64) sW2[tid] = W2[tid];
    __syncthreads();

    int e = blockIdx.x * blockDim.x + tid;
    if (e >= E) return;
    int m = mi[e], d = di[e];

    const uint4* pm = (const uint4*)(g_pmh + (size_t)m * 32);  // 8 x uint4 per row
    const uint4* pd = (const uint4*)(g_pdh + (size_t)d * 32);

    float score = 0.f;
#pragma unroll
    for (int q = 0; q < 8; q++) {
        uint4 ua = pm[q];
        uint4 ub = pd[q];
        const unsigned* ap = (const unsigned*)&ua;
        const unsigned* bp = (const unsigned*)&ub;
#pragma unroll
        for (int s = 0; s < 4; s++) {
            float2 fa = __half22float2(*(const __half2*)&ap[s]);
            float2 fb = __half22float2(*(const __half2*)&bp[s]);
            int j = q * 8 + s * 2;
            score += tanh_approx(fa.x + fb.x) * sW2[j + 0];
            score += tanh_approx(fa.y + fb.y) * sW2[j + 1];
        }
    }
    float w = __expf(score);
    int pmpos = atomicAdd(&g_cur_m[m], 1);
    g_col_m[pmpos] = d; g_val_m[pmpos] = w;
    int pdpos = atomicAdd(&g_cur_d[d], 1);
    g_col_d[pdpos] = m; g_val_d[pdpos] = w;
}

// ---------------- CSR SpMM (half gathers) + fused rowsum on layer 1 -------
// one warp per row; lane handles one half2 (2 of 64 cols)
// store==1: also computes row sum of val (warp-uniform) -> g_rs for layers 2-3
__global__ __launch_bounds__(256) void spmm_kernel(float* __restrict__ outacc,
                                                   int dir, int store) {
    const int*     off  = dir ? g_off_d : g_off_m;
    const int*     cur  = dir ? g_cur_d : g_cur_m;
    const int*     col  = dir ? g_col_d : g_col_m;
    const float*   val  = dir ? g_val_d : g_val_m;
    float*         rs   = dir ? g_rs_d : g_rs_m;
    const __half2* xin  = dir ? g_membh : g_dembh;
    __half2*       xout = dir ? g_dembh : g_membh;
    int nrows = dir ? ND : NM;

    int gwarp = (blockIdx.x * blockDim.x + threadIdx.x) >> 5;
    int lane = threadIdx.x & 31;
    if (gwarp >= nrows) return;
    int t = off[gwarp], epos = cur[gwarp];

    float a0 = 0.f, a1 = 0.f, vsum = 0.f;
    for (; t + 8 <= epos; t += 8) {
        int4   ca = *(const int4*)(col + t);
        int4   cb = *(const int4*)(col + t + 4);
        float4 va = *(const float4*)(val + t);
        float4 vb = *(const float4*)(val + t + 4);
        __half2 x0 = xin[(size_t)ca.x * 32 + lane];
        __half2 x1 = xin[(size_t)ca.y * 32 + lane];
        __half2 x2 = xin[(size_t)ca.z * 32 + lane];
        __half2 x3 = xin[(size_t)ca.w * 32 + lane];
        __half2 x4 = xin[(size_t)cb.x * 32 + lane];
        __half2 x5 = xin[(size_t)cb.y * 32 + lane];
        __half2 x6 = xin[(size_t)cb.z * 32 + lane];
        __half2 x7 = xin[(size_t)cb.w * 32 + lane];
        if (store)
            vsum += (va.x + va.y + va.z + va.w) + (vb.x + vb.y + vb.z + vb.w);
        float2 f;
        f = __half22float2(x0); a0 += va.x * f.x; a1 += va.x * f.y;
        f = __half22float2(x1); a0 += va.y * f.x; a1 += va.y * f.y;
        f = __half22float2(x2); a0 += va.z * f.x; a1 += va.z * f.y;
        f = __half22float2(x3); a0 += va.w * f.x; a1 += va.w * f.y;
        f = __half22float2(x4); a0 += vb.x * f.x; a1 += vb.x * f.y;
        f = __half22float2(x5); a0 += vb.y * f.x; a1 += vb.y * f.y;
        f = __half22float2(x6); a0 += vb.z * f.x; a1 += vb.z * f.y;
        f = __half22float2(x7); a0 += vb.w * f.x; a1 += vb.w * f.y;
    }
    for (; t < epos; t++) {
        int c = col[t]; float v = val[t];
        if (store) vsum += v;
        float2 f = __half22float2(xin[(size_t)c * 32 + lane]);
        a0 += v * f.x; a1 += v * f.y;
    }

    float inv;
    if (store) {
        inv = (vsum > 0.f) ? rsqrtf(vsum) : 0.f;   // identical in all lanes
        if (lane == 0) rs[gwarp] = inv;
    } else {
        inv = rs[gwarp];
    }
    float y0 = tanh_fast(a0 * inv);
    float y1 = tanh_fast(a1 * inv);
    xout[(size_t)gwarp * 32 + lane] = __float22half2_rn(make_float2(y0, y1));
    float* oa = outacc + (size_t)gwarp * DIM + lane * 2;
    if (store) { oa[0] = y0; oa[1] = y1; }
    else       { oa[0] += y0; oa[1] += y1; }
}

// ---------------- launch ----------------
extern "C" void kernel_launch(void* const* d_in, const int* in_sizes, int n_in,
                              void* d_out, int out_size) {
    const float* m_sim = (const float*)d_in[0];
    const float* d_sim = (const float*)d_in[1];
    const float* Wm    = (const float*)d_in[2];
    const float* Wd    = (const float*)d_in[3];
    const float* W1    = (const float*)d_in[4];
    const float* b1    = (const float*)d_in[5];
    const float* W2    = (const float*)d_in[6];
    const int*   mi    = (const int*)d_in[7];
    const int*   di    = (const int*)d_in[8];
    int E = in_sizes[7];
    float* out = (float*)d_out;

    zero_kernel<<<(NM + 255) / 256, 256>>>();
    proj_mma_kernel<<<GRID_PB + NCOUNT, 128>>>(m_sim, d_sim, Wm, Wd, mi, di, E);
    scan_kernel<<<2, 1024>>>();
    pre_mlp_both_kernel<<<GRID_PB, 256>>>(W1, b1);
    edge_csr_kernel<<<(E + 255) / 256, 256>>>(W2, mi, di, E);

    float* out_m = out;
    float* out_d = out + (size_t)NM * DIM;
    for (int l = 0; l < LAYERS; l++) {
        spmm_kernel<<<(NM * 32 + 255) / 256, 256>>>(out_m, 0, l == 0);
        spmm_kernel<<<(ND * 32 + 255) / 256, 256>>>(out_d, 1, l == 0);
    }
}